// round 2
// baseline (speedup 1.0000x reference)
#include <cuda_runtime.h>
#include <cuda_bf16.h>
#include <math.h>

// Problem constants
#define BB 256
#define II 1152
#define OO 10
#define FF 8
#define GG 16
#define OG 160            // OO*GG
#define IOG 184320        // II*OG
#define XN 2359296        // BB*II*FF
#define WN 1474560        // II*OO*FF*GG
#define VN 40960          // BB*OO*GG
#define UN 47185920       // BB*II*OO*GG

// ---------------------------------------------------------------------------
// K1: u[b,i,o,g] = sum_f x[b,i,f] * W[i,o,f,g]
// One block per i. 320 threads = (og 0..159) x (half 0..1).
// x[:,i,:] staged in smem; W[i, o, :, g] held in 8 registers per thread.
// Writes are coalesced: warp lanes span contiguous og (160 = 5 warps exactly).
// ---------------------------------------------------------------------------
__global__ void __launch_bounds__(320) caps_u_kernel(
    const float* __restrict__ x, const float* __restrict__ W,
    float* __restrict__ u)
{
    const int i = blockIdx.x;
    __shared__ float xs[BB][FF];   // 8 KB

    const int t = threadIdx.x;
    const float* xg = x + (size_t)i * FF;
    for (int idx = t; idx < BB * FF; idx += 320) {
        int b = idx >> 3, f = idx & 7;
        xs[b][f] = xg[(size_t)b * (II * FF) + f];
    }

    const int og = t % OG;          // 0..159
    const int half = t / OG;        // 0 or 1
    const int o = og >> 4, g = og & 15;

    float w[FF];
    const float* Wp = W + (size_t)i * (OO * FF * GG) + o * (FF * GG) + g;
#pragma unroll
    for (int f = 0; f < FF; f++) w[f] = Wp[f * GG];

    __syncthreads();

    float* up = u + (size_t)i * OG + og;
#pragma unroll 4
    for (int b = half; b < BB; b += 2) {
        float4 x0 = *(const float4*)&xs[b][0];
        float4 x1 = *(const float4*)&xs[b][4];
        float acc = x0.x * w[0] + x0.y * w[1] + x0.z * w[2] + x0.w * w[3]
                  + x1.x * w[4] + x1.y * w[5] + x1.z * w[6] + x1.w * w[7];
        up[(size_t)b * IOG] = acc;
    }
}

// ---------------------------------------------------------------------------
// K2: dynamic routing, one block per (b,o). Register-resident:
// 288 threads; each thread owns 4 rows of the [1152,16] u-slice (64 regs)
// plus their 4 logits. Only tiny static smem for block reductions.
// ---------------------------------------------------------------------------
__global__ void __launch_bounds__(288) caps_route_kernel(
    const float* __restrict__ u, float* __restrict__ vout)
{
    const int bo = blockIdx.x;
    const int b = bo / OO, o = bo % OO;

    __shared__ float red[9][17];   // per-warp partials: z + S[16]
    __shared__ float vsh[GG];      // broadcast v
    __shared__ float msh[9];       // per-warp max

    const int tid = threadIdx.x;
    const int lane = tid & 31, wid = tid >> 5;   // 9 warps

    // Load 4 rows: i = tid + 288*r. Each row = 64 contiguous bytes.
    float ul[4][GG];
    float lg[4] = {0.f, 0.f, 0.f, 0.f};
    const float* ub = u + (size_t)b * IOG + o * GG;
#pragma unroll
    for (int r = 0; r < 4; r++) {
        const float* p = ub + (size_t)(tid + 288 * r) * OG;
#pragma unroll
        for (int q = 0; q < 4; q++) {
            float4 v4 = *(const float4*)(p + q * 4);
            ul[r][q * 4 + 0] = v4.x; ul[r][q * 4 + 1] = v4.y;
            ul[r][q * 4 + 2] = v4.z; ul[r][q * 4 + 3] = v4.w;
        }
    }

#pragma unroll
    for (int step = 0; step < 3; step++) {
        // ---- max over logits (softmax numerical safety) ----
        float mloc = fmaxf(fmaxf(lg[0], lg[1]), fmaxf(lg[2], lg[3]));
#pragma unroll
        for (int off = 16; off; off >>= 1)
            mloc = fmaxf(mloc, __shfl_xor_sync(0xffffffffu, mloc, off));
        if (lane == 0) msh[wid] = mloc;
        __syncthreads();
        float M = msh[0];
#pragma unroll
        for (int wi = 1; wi < 9; wi++) M = fmaxf(M, msh[wi]);

        // ---- z = sum exp, S[g] = sum exp * u ----
        float e[4];
        float z = 0.f;
#pragma unroll
        for (int r = 0; r < 4; r++) { e[r] = __expf(lg[r] - M); z += e[r]; }
        float sv[GG];
#pragma unroll
        for (int g2 = 0; g2 < GG; g2++)
            sv[g2] = e[0] * ul[0][g2] + e[1] * ul[1][g2]
                   + e[2] * ul[2][g2] + e[3] * ul[3][g2];
#pragma unroll
        for (int off = 16; off; off >>= 1) {
            z += __shfl_xor_sync(0xffffffffu, z, off);
#pragma unroll
            for (int g2 = 0; g2 < GG; g2++)
                sv[g2] += __shfl_xor_sync(0xffffffffu, sv[g2], off);
        }
        if (lane == 0) {
            red[wid][0] = z;
#pragma unroll
            for (int g2 = 0; g2 < GG; g2++) red[wid][1 + g2] = sv[g2];
        }
        __syncthreads();

        // ---- squash (thread 0; trivial) ----
        if (tid == 0) {
            float Z = 0.f, S[GG];
#pragma unroll
            for (int g2 = 0; g2 < GG; g2++) S[g2] = 0.f;
#pragma unroll
            for (int wi = 0; wi < 9; wi++) {
                Z += red[wi][0];
#pragma unroll
                for (int g2 = 0; g2 < GG; g2++) S[g2] += red[wi][1 + g2];
            }
            float inv = 1.f / Z;
            float n2 = 0.f;
#pragma unroll
            for (int g2 = 0; g2 < GG; g2++) {
                float sgv = S[g2] * inv;
                S[g2] = sgv;
                n2 += sgv * sgv;
            }
            float n = sqrtf(n2);
            float fac = n / (n2 + 1.f);
#pragma unroll
            for (int g2 = 0; g2 < GG; g2++) vsh[g2] = S[g2] * fac;
        }
        __syncthreads();

        // ---- logits += u . v (skip on last step) ----
        if (step < 2) {
#pragma unroll
            for (int r = 0; r < 4; r++) {
                float d = 0.f;
#pragma unroll
                for (int g2 = 0; g2 < GG; g2++) d += ul[r][g2] * vsh[g2];
                lg[r] += d;
            }
            __syncthreads();   // protect vsh before next step's rewrite
        }
    }

    if (tid < GG) vout[(size_t)bo * GG + tid] = vsh[tid];
}

// ---------------------------------------------------------------------------
extern "C" void kernel_launch(void* const* d_in, const int* in_sizes, int n_in,
                              void* d_out, int out_size)
{
    const float *x = (const float*)d_in[0];
    const float *W = (const float*)d_in[1];
    if (n_in >= 2 && in_sizes[0] == WN && in_sizes[1] == XN) {
        x = (const float*)d_in[1];
        W = (const float*)d_in[0];
    }

    float* out = (float*)d_out;
    float* vout = out;
    float* uout = out;
    if (out_size >= VN + UN) {          // (v, u_dash) concatenated in tuple order
        vout = out;
        uout = out + VN;
    } else if (out_size >= UN) {        // u_dash only (fallback)
        uout = out;
        vout = out;
    }

    caps_u_kernel<<<II, 320>>>(x, W, uout);
    caps_route_kernel<<<BB * OO, 288>>>(uout, vout);
}

// round 5
// speedup vs baseline: 1.0910x; 1.0910x over previous
#include <cuda_runtime.h>
#include <cuda_bf16.h>
#include <math.h>

// Problem constants
#define BB 256
#define II 1152
#define OO 10
#define FF 8
#define GG 16
#define OG 160            // OO*GG
#define IOG 184320        // II*OG
#define XN 2359296        // BB*II*FF
#define WN 1474560        // II*OO*FF*GG
#define VN 40960          // BB*OO*GG
#define UN 47185920       // BB*II*OO*GG

// ---------------------------------------------------------------------------
// K1: u[b,i,o,g] = sum_f x[b,i,f] * W[i,o,f,g]
// grid (II, 2): block (i, yhalf) handles 128 b's. 320 threads = og x bparity.
// x[:,i,:] staged in smem; W[i,o,:,g] in 8 registers; coalesced og writes.
// ---------------------------------------------------------------------------
__global__ void __launch_bounds__(320) caps_u_kernel(
    const float* __restrict__ x, const float* __restrict__ W,
    float* __restrict__ u)
{
    const int i = blockIdx.x;
    const int b0 = blockIdx.y * (BB / 2);
    __shared__ float xs[BB / 2][FF];   // 4 KB

    const int t = threadIdx.x;
    const float* xg = x + (size_t)i * FF;
    for (int idx = t; idx < (BB / 2) * FF; idx += 320) {
        int b = idx >> 3, f = idx & 7;
        xs[b][f] = xg[(size_t)(b0 + b) * (II * FF) + f];
    }

    const int og = t % OG;          // 0..159
    const int half = t / OG;        // 0 or 1
    const int o = og >> 4, g = og & 15;

    float w[FF];
    const float* Wp = W + (size_t)i * (OO * FF * GG) + o * (FF * GG) + g;
#pragma unroll
    for (int f = 0; f < FF; f++) w[f] = Wp[f * GG];

    __syncthreads();

    float* up = u + (size_t)i * OG + og + (size_t)b0 * IOG;
#pragma unroll 4
    for (int b = half; b < BB / 2; b += 2) {
        float4 x0 = *(const float4*)&xs[b][0];
        float4 x1 = *(const float4*)&xs[b][4];
        float acc = x0.x * w[0] + x0.y * w[1] + x0.z * w[2] + x0.w * w[3]
                  + x1.x * w[4] + x1.y * w[5] + x1.z * w[6] + x1.w * w[7];
        up[(size_t)b * IOG] = acc;
    }
}

// ---------------------------------------------------------------------------
// K2: dynamic routing, one block per (b,o). 512 threads = 32 i-groups x 16 g.
// Thread (it, g) holds u[b, it+32k, o, g] for k=0..35 in registers (36 regs).
// Logits + exp table in static smem. No softmax max-subtraction (logits are
// bounded: |logit| <= 2 * ||u_row|| * ||v|| < 23, exp is safe in fp32).
// ---------------------------------------------------------------------------
#define RPT 36      // rows per thread: 1152 / 32
#define K2T 512

__global__ void __launch_bounds__(K2T, 2) caps_route_kernel(
    const float* __restrict__ u, float* __restrict__ vout)
{
    const int bo = blockIdx.x;
    const int b = bo / OO, o = bo % OO;

    __shared__ float lg[II];        // logits
    __shared__ float esh[II];       // exp(logits)
    __shared__ float red[32][GG];   // S partials per i-group
    __shared__ float redz[32];      // z partials per i-group
    __shared__ float vsh[GG];

    const int tid = threadIdx.x;
    const int g  = tid & 15;        // 0..15
    const int it = tid >> 4;        // 0..31

    // ---- load u: warp = 2 i-groups x 16 g -> two 64B fully-used segments ----
    float ureg[RPT];
    const float* ub = u + (size_t)b * IOG + o * GG + g;
#pragma unroll
    for (int k = 0; k < RPT; k++)
        ureg[k] = ub[(size_t)(it + 32 * k) * OG];

    for (int i = tid; i < II; i += K2T) lg[i] = 0.f;
    __syncthreads();

#pragma unroll
    for (int step = 0; step < 3; step++) {
        // ---- e[i] = exp(lg[i]), computed once per i ----
        for (int i = tid; i < II; i += K2T) esh[i] = __expf(lg[i]);
        __syncthreads();

        // ---- scalar partials: s = sum_k e*u, z = sum_k e ----
        float s = 0.f, z = 0.f;
#pragma unroll
        for (int k = 0; k < RPT; k++) {
            float e = esh[it + 32 * k];    // broadcast LDS
            s += e * ureg[k];
            z += e;
        }
        red[it][g] = s;
        if (g == 0) redz[it] = z;
        __syncthreads();

        // ---- tree reduce over 32 i-groups ----
#pragma unroll
        for (int off = 16; off; off >>= 1) {
            if (it < off) {
                red[it][g] += red[it + off][g];
                if (g == 0) redz[it] += redz[it + off];
            }
            __syncthreads();
        }

        // ---- squash (thread 0) ----
        if (tid == 0) {
            float inv = 1.f / redz[0];
            float n2 = 0.f;
            float S[GG];
#pragma unroll
            for (int g2 = 0; g2 < GG; g2++) {
                float sg = red[0][g2] * inv;
                S[g2] = sg;
                n2 += sg * sg;
            }
            float n = sqrtf(n2);
            float fac = n / (n2 + 1.f);
#pragma unroll
            for (int g2 = 0; g2 < GG; g2++) vsh[g2] = S[g2] * fac;
        }
        __syncthreads();

        // ---- logits += u . v (skip last step) ----
        if (step < 2) {
            float v = vsh[g];
#pragma unroll
            for (int k = 0; k < RPT; k++) {
                float p = ureg[k] * v;
                p += __shfl_xor_sync(0xffffffffu, p, 8);
                p += __shfl_xor_sync(0xffffffffu, p, 4);
                p += __shfl_xor_sync(0xffffffffu, p, 2);
                p += __shfl_xor_sync(0xffffffffu, p, 1);
                if (g == 0) lg[it + 32 * k] += p;
            }
            __syncthreads();
        }
    }

    if (tid < GG) vout[(size_t)bo * GG + tid] = vsh[tid];
}

// ---------------------------------------------------------------------------
extern "C" void kernel_launch(void* const* d_in, const int* in_sizes, int n_in,
                              void* d_out, int out_size)
{
    const float *x = (const float*)d_in[0];
    const float *W = (const float*)d_in[1];
    if (n_in >= 2 && in_sizes[0] == WN && in_sizes[1] == XN) {
        x = (const float*)d_in[1];
        W = (const float*)d_in[0];
    }

    float* out = (float*)d_out;
    float* vout = out;
    float* uout = out;
    if (out_size >= VN + UN) {          // (v, u_dash) concatenated in tuple order
        vout = out;
        uout = out + VN;
    } else if (out_size >= UN) {        // u_dash only (fallback)
        uout = out;
        vout = out;
    }

    dim3 g1(II, 2);
    caps_u_kernel<<<g1, 320>>>(x, W, uout);
    caps_route_kernel<<<BB * OO, K2T>>>(uout, vout);
}